// round 6
// baseline (speedup 1.0000x reference)
#include <cuda_runtime.h>
#include <cuda_bf16.h>
#include <math.h>

// Problem constants
#define HIDDEN    2560
#define NUM_HEADS 8
#define HEAD_DIM  512
#define SEQ       32768
#define QROWS     (NUM_HEADS * HEAD_DIM)   // 4096
#define SCALE     0.04419417382415922f     // 1/sqrt(512)

#define CHUNK     64                       // keys per attention block
#define NCHUNK    (SEQ / CHUNK)            // 512 blocks
#define NGROUP    16                       // reduce groups
#define GSZ       (NCHUNK / NGROUP)        // 32 chunks per group

typedef unsigned long long u64;

// ------------------------- device scratch (no allocs allowed) ---------------
__device__ __align__(16) float g_q[QROWS];
__device__ __align__(16) float g_k[HEAD_DIM];
__device__ __align__(16) float g_v[HEAD_DIM];
__device__ float g_pm[NCHUNK * NUM_HEADS];          // per-chunk max
__device__ float g_pl[NCHUNK * NUM_HEADS];          // per-chunk expsum
__device__ __align__(16) float g_pacc[(size_t)NCHUNK * QROWS];    // 8 MB
__device__ __align__(16) float g_pacc2[(size_t)NGROUP * QROWS];   // 256 KB

// ------------------------- helpers ------------------------------------------
__device__ __forceinline__ float warp_sum(float v) {
    #pragma unroll
    for (int o = 16; o; o >>= 1) v += __shfl_xor_sync(0xffffffffu, v, o);
    return v;
}
__device__ __forceinline__ float warp_max(float v) {
    #pragma unroll
    for (int o = 16; o; o >>= 1) v = fmaxf(v, __shfl_xor_sync(0xffffffffu, v, o));
    return v;
}
// packed fp32x2 ops (Blackwell PTX-only; doubles fp32 FMA rate)
__device__ __forceinline__ void fma2(u64& d, u64 a, u64 b) {
    asm("fma.rn.f32x2 %0, %1, %2, %0;" : "+l"(d) : "l"(a), "l"(b));
}
__device__ __forceinline__ void add2(u64& d, u64 a) {
    asm("add.rn.f32x2 %0, %1, %0;" : "+l"(d) : "l"(a));
}
__device__ __forceinline__ float2 unpack2(u64 v) {
    unsigned lo, hi;
    asm("mov.b64 {%0, %1}, %2;" : "=r"(lo), "=r"(hi) : "l"(v));
    return make_float2(__uint_as_float(lo), __uint_as_float(hi));
}

// ------------------------- kernel 1: fused QKV GEMV (warp-per-row) -----------
__global__ void __launch_bounds__(1024)
qkv_gemv(const float* __restrict__ x,
         const float* __restrict__ wq,
         const float* __restrict__ wk,
         const float* __restrict__ wv) {
    int r = blockIdx.x * 32 + (threadIdx.x >> 5);
    int lane = threadIdx.x & 31;
    const float* w;
    float* out;
    if (r < QROWS)            { w = wq + (size_t)r * HIDDEN;                 out = g_q + r; }
    else if (r < QROWS + 512) { w = wk + (size_t)(r - QROWS) * HIDDEN;       out = g_k + (r - QROWS); }
    else                      { w = wv + (size_t)(r - QROWS - 512) * HIDDEN; out = g_v + (r - QROWS - 512); }

    const float4* w4 = reinterpret_cast<const float4*>(w);
    const float4* x4 = reinterpret_cast<const float4*>(x);
    float s = 0.f;
    #pragma unroll
    for (int i = 0; i < HIDDEN / 4 / 32; i++) {     // 20 iterations
        float4 a = w4[i * 32 + lane];
        float4 b = x4[i * 32 + lane];
        s += a.x * b.x + a.y * b.y + a.z * b.z + a.w * b.w;
    }
    s = warp_sum(s);
    if (lane == 0) *out = s;
}

// ------------------------- kernel 2: fused flash-decode chunk ----------------
// 512 blocks x 256 threads. Each block: 64 keys. f32x2 packed math throughout.
__global__ void __launch_bounds__(256, 3)
attn_chunk(const float* __restrict__ kv_full, const int* __restrict__ cur_pos) {
    __shared__ __align__(16) float qs[QROWS];                 // 16 KB (reused in C)
    __shared__ __align__(16) float p2[NUM_HEADS][CHUNK][2];   // probs duplicated, 4 KB

    for (int i = threadIdx.x; i < QROWS; i += 256) qs[i] = g_q[i];
    __syncthreads();

    const int warp = threadIdx.x >> 5, lane = threadIdx.x & 31;
    const int cp = cur_pos[0];
    const int j0 = blockIdx.x * CHUNK;

    // ---- Phase A: scores (8 warps x 8 keys; 2 keys concurrently per warp) ----
    #pragma unroll
    for (int g = 0; g < 4; g++) {
        const int jj = warp * 8 + g * 2;
        const int ja = j0 + jj, jb = j0 + jj + 1;
        const float* k0p = (ja == cp) ? g_k : (kv_full + (size_t)ja * HEAD_DIM);
        const float* k1p = (jb == cp) ? g_k : (kv_full + (size_t)jb * HEAD_DIM);

        u64 acc0[NUM_HEADS], acc1[NUM_HEADS];
        #pragma unroll
        for (int h = 0; h < NUM_HEADS; h++) { acc0[h] = 0ull; acc1[h] = 0ull; }

        #pragma unroll
        for (int i = 0; i < 4; i++) {
            int d = i * 128 + lane * 4;
            ulonglong2 k0 = *reinterpret_cast<const ulonglong2*>(k0p + d);
            ulonglong2 k1 = *reinterpret_cast<const ulonglong2*>(k1p + d);
            #pragma unroll
            for (int h = 0; h < NUM_HEADS; h++) {
                ulonglong2 qv = *reinterpret_cast<const ulonglong2*>(qs + h * HEAD_DIM + d);
                fma2(acc0[h], qv.x, k0.x);
                fma2(acc0[h], qv.y, k0.y);
                fma2(acc1[h], qv.x, k1.x);
                fma2(acc1[h], qv.y, k1.y);
            }
        }
        #pragma unroll
        for (int h = 0; h < NUM_HEADS; h++) {
            float2 f0 = unpack2(acc0[h]);
            float2 f1 = unpack2(acc1[h]);
            float s0 = warp_sum(f0.x + f0.y);
            float s1 = warp_sum(f1.x + f1.y);
            if (lane == 0) {
                p2[h][jj][0]     = s0 * SCALE;
                p2[h][jj + 1][0] = s1 * SCALE;
            }
        }
    }
    __syncthreads();

    // ---- Phase B: local softmax stats; write duplicated probs ----
    {
        const int h = warp;
        float a = p2[h][lane][0];
        float b = p2[h][lane + 32][0];
        float m = warp_max(fmaxf(a, b));
        float ea = __expf(a - m);
        float eb = __expf(b - m);
        float l = warp_sum(ea + eb);
        p2[h][lane][0]      = ea;  p2[h][lane][1]      = ea;
        p2[h][lane + 32][0] = eb;  p2[h][lane + 32][1] = eb;
        if (lane == 0) {
            g_pm[blockIdx.x * NUM_HEADS + h] = m;
            g_pl[blockIdx.x * NUM_HEADS + h] = l;
        }
    }
    __syncthreads();

    // ---- Phase C: P @ V partial (packed f32x2, jj split across halves) ----
    const int half = threadIdx.x >> 7;          // 0 or 1
    const int t    = threadIdx.x & 127;
    const int d    = t * 4;
    const int jbase = half * 32;
    const float* vcache = kv_full + (size_t)SEQ * HEAD_DIM;

    u64 alo[NUM_HEADS], ahi[NUM_HEADS];
    #pragma unroll
    for (int h = 0; h < NUM_HEADS; h++) { alo[h] = 0ull; ahi[h] = 0ull; }

    #pragma unroll 8
    for (int jj = 0; jj < 32; jj++) {
        int j = j0 + jbase + jj;
        const float* vrow = (j == cp) ? g_v : (vcache + (size_t)j * HEAD_DIM);
        ulonglong2 vv = *reinterpret_cast<const ulonglong2*>(vrow + d);
        #pragma unroll
        for (int h = 0; h < NUM_HEADS; h++) {
            u64 pw2 = *reinterpret_cast<const u64*>(&p2[h][jbase + jj][0]);
            fma2(alo[h], pw2, vv.x);
            fma2(ahi[h], pw2, vv.y);
        }
    }

    // combine halves via smem (reuse qs as ulonglong2[8][128] = 16 KB)
    __syncthreads();
    ulonglong2* cb = reinterpret_cast<ulonglong2*>(qs);
    if (half == 1) {
        #pragma unroll
        for (int h = 0; h < NUM_HEADS; h++) {
            ulonglong2 v; v.x = alo[h]; v.y = ahi[h];
            cb[h * 128 + t] = v;
        }
    }
    __syncthreads();
    if (half == 0) {
        float* o = g_pacc + (size_t)blockIdx.x * QROWS;
        #pragma unroll
        for (int h = 0; h < NUM_HEADS; h++) {
            ulonglong2 v = cb[h * 128 + t];
            add2(alo[h], v.x);
            add2(ahi[h], v.y);
            float2 lo = unpack2(alo[h]);
            float2 hi = unpack2(ahi[h]);
            *reinterpret_cast<float4*>(o + h * HEAD_DIM + d) =
                make_float4(lo.x, lo.y, hi.x, hi.y);
        }
    }
}

// ------------------------- kernel 3: weighted reduce L1 (+ fused stats) ------
// 256 blocks x 256 thr. Block: group g (32 chunks) x 256 outputs (one head).
// 4-way chunk split, float4 loads (8 independent LDG.128 per thread).
__global__ void __launch_bounds__(256)
reduce1() {
    const int g  = blockIdx.x >> 4;             // 0..15
    const int ib = blockIdx.x & 15;             // 0..15
    const int h  = ib >> 1;                     // head for this block

    __shared__ float red[8];
    __shared__ float sM, sL;
    __shared__ float w[GSZ];
    __shared__ __align__(16) float4 red4[4][64];
    const int lane = threadIdx.x & 31, warp = threadIdx.x >> 5;

    // global max over all 512 chunks for head h
    float m = fmaxf(g_pm[(threadIdx.x * 2) * NUM_HEADS + h],
                    g_pm[(threadIdx.x * 2 + 1) * NUM_HEADS + h]);
    m = warp_max(m);
    if (lane == 0) red[warp] = m;
    __syncthreads();
    if (threadIdx.x == 0) {
        float M = red[0];
        #pragma unroll
        for (int i = 1; i < 8; i++) M = fmaxf(M, red[i]);
        sM = M;
    }
    __syncthreads();
    float l = g_pl[(threadIdx.x * 2) * NUM_HEADS + h] * __expf(g_pm[(threadIdx.x * 2) * NUM_HEADS + h] - sM)
            + g_pl[(threadIdx.x * 2 + 1) * NUM_HEADS + h] * __expf(g_pm[(threadIdx.x * 2 + 1) * NUM_HEADS + h] - sM);
    l = warp_sum(l);
    __syncthreads();
    if (lane == 0) red[warp] = l;
    __syncthreads();
    if (threadIdx.x == 0) {
        float L = 0.f;
        #pragma unroll
        for (int i = 0; i < 8; i++) L += red[i];
        sL = L;
    }
    __syncthreads();
    if (threadIdx.x < GSZ) {
        int c = g * GSZ + threadIdx.x;
        w[threadIdx.x] = __expf(g_pm[c * NUM_HEADS + h] - sM) / sL;
    }
    __syncthreads();

    const int q  = threadIdx.x >> 6;            // chunk quarter 0..3
    const int t4 = threadIdx.x & 63;            // float4 index within 256 outputs
    const int base4 = ib * 64 + t4;             // float4 index within QROWS/4=1024
    const float4* pacc4 = reinterpret_cast<const float4*>(g_pacc);

    float4 s = make_float4(0.f, 0.f, 0.f, 0.f);
    #pragma unroll
    for (int cc = 0; cc < 8; cc++) {
        int cl = q * 8 + cc;
        float4 v = pacc4[(size_t)(g * GSZ + cl) * (QROWS / 4) + base4];
        float wt = w[cl];
        s.x = fmaf(wt, v.x, s.x);
        s.y = fmaf(wt, v.y, s.y);
        s.z = fmaf(wt, v.z, s.z);
        s.w = fmaf(wt, v.w, s.w);
    }
    red4[q][t4] = s;
    __syncthreads();
    if (q == 0) {
        float4 a = red4[1][t4], b = red4[2][t4], c = red4[3][t4];
        s.x += a.x + b.x + c.x;
        s.y += a.y + b.y + c.y;
        s.z += a.z + b.z + c.z;
        s.w += a.w + b.w + c.w;
        reinterpret_cast<float4*>(g_pacc2)[(size_t)g * (QROWS / 4) + base4] = s;
    }
}

// ------------------------- kernel 4: output GEMV (fused final reduce) --------
// 80 blocks x 1024 threads. Prologue: sum 16 groups (L2) -> attn in smem.
__global__ void __launch_bounds__(1024)
wo_gemv(const float* __restrict__ wo, float* __restrict__ out) {
    __shared__ __align__(16) float attn[QROWS];

    #pragma unroll
    for (int e = 0; e < 4; e++) {
        int idx = e * 1024 + threadIdx.x;
        float s = 0.f;
        #pragma unroll
        for (int g = 0; g < NGROUP; g++) s += g_pacc2[(size_t)g * QROWS + idx];
        attn[idx] = s;
    }
    __syncthreads();

    int r = blockIdx.x * 32 + (threadIdx.x >> 5);
    int lane = threadIdx.x & 31;
    const float4* w4 = reinterpret_cast<const float4*>(wo + (size_t)r * QROWS);
    const float4* a4 = reinterpret_cast<const float4*>(attn);
    float s = 0.f;
    #pragma unroll
    for (int i = 0; i < QROWS / 4 / 32; i++) {      // 32 iterations
        float4 a = w4[i * 32 + lane];
        float4 b = a4[i * 32 + lane];
        s += a.x * b.x + a.y * b.y + a.z * b.z + a.w * b.w;
    }
    s = warp_sum(s);
    if (lane == 0) out[r] = s;
}

// ------------------------- launch -------------------------------------------
extern "C" void kernel_launch(void* const* d_in, const int* in_sizes, int n_in,
                              void* d_out, int out_size) {
    const float* x       = (const float*)d_in[0];
    // d_in[1] = kv_sliding (unused by reference math)
    const float* kv_full = (const float*)d_in[2];
    const float* wq      = (const float*)d_in[3];
    const float* wk      = (const float*)d_in[4];
    const float* wv      = (const float*)d_in[5];
    const float* wo      = (const float*)d_in[6];
    const int*   curpos  = (const int*)d_in[7];
    // d_in[8] = ring_pos (unused)
    float* out = (float*)d_out;

    qkv_gemv<<<160, 1024>>>(x, wq, wk, wv);
    attn_chunk<<<NCHUNK, 256>>>(kv_full, curpos);
    reduce1<<<NGROUP * 16, 256>>>();
    wo_gemv<<<80, 1024>>>(wo, out);
}

// round 7
// speedup vs baseline: 1.9052x; 1.9052x over previous
#include <cuda_runtime.h>
#include <cuda_bf16.h>
#include <math.h>

// Problem constants
#define HIDDEN    2560
#define NUM_HEADS 8
#define HEAD_DIM  512
#define SEQ       32768
#define QROWS     (NUM_HEADS * HEAD_DIM)   // 4096
#define SCALE     0.04419417382415922f     // 1/sqrt(512)

#define CHUNK     64                       // keys per attention block
#define NCHUNK    (SEQ / CHUNK)            // 512 blocks

// ------------------------- device scratch (no allocs allowed) ---------------
__device__ __align__(16) float g_q[QROWS];
__device__ __align__(16) float g_k[HEAD_DIM];
__device__ __align__(16) float g_v[HEAD_DIM];
__device__ float g_pm[NCHUNK * NUM_HEADS];          // per-chunk max
__device__ float g_pl[NCHUNK * NUM_HEADS];          // per-chunk expsum
__device__ __align__(16) float g_pacc[(size_t)NCHUNK * QROWS];    // 8 MB
__device__ __align__(16) float g_attn[QROWS];

// ------------------------- helpers ------------------------------------------
__device__ __forceinline__ float warp_sum(float v) {
    #pragma unroll
    for (int o = 16; o; o >>= 1) v += __shfl_xor_sync(0xffffffffu, v, o);
    return v;
}
__device__ __forceinline__ float warp_max(float v) {
    #pragma unroll
    for (int o = 16; o; o >>= 1) v = fmaxf(v, __shfl_xor_sync(0xffffffffu, v, o));
    return v;
}
__device__ __forceinline__ float4 ldcs4(const float* p) {
    return __ldcs(reinterpret_cast<const float4*>(p));
}

// ------------------------- kernel 1: fused QKV GEMV (warp-per-row) -----------
// 160 blocks x 1024 threads = 5120 warps; warp w handles row w.
__global__ void __launch_bounds__(1024)
qkv_gemv(const float* __restrict__ x,
         const float* __restrict__ wq,
         const float* __restrict__ wk,
         const float* __restrict__ wv) {
    int r = blockIdx.x * 32 + (threadIdx.x >> 5);
    int lane = threadIdx.x & 31;
    const float* w;
    float* out;
    if (r < QROWS)            { w = wq + (size_t)r * HIDDEN;                 out = g_q + r; }
    else if (r < QROWS + 512) { w = wk + (size_t)(r - QROWS) * HIDDEN;       out = g_k + (r - QROWS); }
    else                      { w = wv + (size_t)(r - QROWS - 512) * HIDDEN; out = g_v + (r - QROWS - 512); }

    const float4* x4 = reinterpret_cast<const float4*>(x);
    float s = 0.f;
    #pragma unroll
    for (int i = 0; i < HIDDEN / 4 / 32; i++) {     // 20 iterations
        float4 a = __ldcs(reinterpret_cast<const float4*>(w) + i * 32 + lane);
        float4 b = x4[i * 32 + lane];
        s += a.x * b.x + a.y * b.y + a.z * b.z + a.w * b.w;
    }
    s = warp_sum(s);
    if (lane == 0) *out = s;
}

// ------------------------- kernel 2: fused flash-decode chunk ----------------
// 512 blocks x 256 threads. Each block: 64 keys. (round-5 float4 structure)
__global__ void __launch_bounds__(256)
attn_chunk(const float* __restrict__ kv_full, const int* __restrict__ cur_pos) {
    __shared__ __align__(16) float qs[QROWS];          // 16 KB (reused as combine buf)
    __shared__ float p[NUM_HEADS][CHUNK];              // scores -> probs, 2 KB

    for (int i = threadIdx.x; i < QROWS; i += 256) qs[i] = g_q[i];
    __syncthreads();

    const int warp = threadIdx.x >> 5, lane = threadIdx.x & 31;
    const int cp = cur_pos[0];
    const int j0 = blockIdx.x * CHUNK;

    // ---- Phase A: scores (8 warps x 8 keys; 4 keys concurrently per warp) ----
    #pragma unroll
    for (int g = 0; g < 2; g++) {
        const int jj = warp * 8 + g * 4;
        const float* kr[4];
        #pragma unroll
        for (int t = 0; t < 4; t++) {
            int j = j0 + jj + t;
            kr[t] = (j == cp) ? g_k : (kv_full + (size_t)j * HEAD_DIM);
        }
        float acc[NUM_HEADS][4];
        #pragma unroll
        for (int h = 0; h < NUM_HEADS; h++)
            #pragma unroll
            for (int t = 0; t < 4; t++) acc[h][t] = 0.f;

        #pragma unroll
        for (int i = 0; i < 4; i++) {
            int d = i * 128 + lane * 4;
            float4 kv0 = ldcs4(kr[0] + d);
            float4 kv1 = ldcs4(kr[1] + d);
            float4 kv2 = ldcs4(kr[2] + d);
            float4 kv3 = ldcs4(kr[3] + d);
            #pragma unroll
            for (int h = 0; h < NUM_HEADS; h++) {
                float4 qv = *reinterpret_cast<const float4*>(qs + h * HEAD_DIM + d);
                acc[h][0] += qv.x * kv0.x + qv.y * kv0.y + qv.z * kv0.z + qv.w * kv0.w;
                acc[h][1] += qv.x * kv1.x + qv.y * kv1.y + qv.z * kv1.z + qv.w * kv1.w;
                acc[h][2] += qv.x * kv2.x + qv.y * kv2.y + qv.z * kv2.z + qv.w * kv2.w;
                acc[h][3] += qv.x * kv3.x + qv.y * kv3.y + qv.z * kv3.z + qv.w * kv3.w;
            }
        }
        #pragma unroll
        for (int h = 0; h < NUM_HEADS; h++) {
            #pragma unroll
            for (int t = 0; t < 4; t++) {
                float s = warp_sum(acc[h][t]);
                if (lane == 0) p[h][jj + t] = s * SCALE;
            }
        }
    }
    __syncthreads();

    // ---- Phase B: local softmax stats (warp h handles head h) ----
    {
        const int h = warp;
        float a = p[h][lane];
        float b = p[h][lane + 32];
        float m = warp_max(fmaxf(a, b));
        float ea = __expf(a - m);
        float eb = __expf(b - m);
        float l = warp_sum(ea + eb);
        p[h][lane]      = ea;
        p[h][lane + 32] = eb;
        if (lane == 0) {
            g_pm[blockIdx.x * NUM_HEADS + h] = m;
            g_pl[blockIdx.x * NUM_HEADS + h] = l;
        }
    }
    __syncthreads();

    // ---- Phase C: P @ V partial (float4, jj split across thread halves) ----
    const int half = threadIdx.x >> 7;          // 0 or 1
    const int t    = threadIdx.x & 127;
    const int d    = t * 4;
    const int jbase = half * 32;
    const float* vcache = kv_full + (size_t)SEQ * HEAD_DIM;

    float4 acc4[NUM_HEADS];
    #pragma unroll
    for (int h = 0; h < NUM_HEADS; h++) acc4[h] = make_float4(0.f, 0.f, 0.f, 0.f);

    #pragma unroll 8
    for (int jj = 0; jj < 32; jj++) {
        int j = j0 + jbase + jj;
        const float* vrow = (j == cp) ? g_v : (vcache + (size_t)j * HEAD_DIM);
        float4 vv = ldcs4(vrow + d);
        #pragma unroll
        for (int h = 0; h < NUM_HEADS; h++) {
            float pw = p[h][jbase + jj];
            acc4[h].x = fmaf(pw, vv.x, acc4[h].x);
            acc4[h].y = fmaf(pw, vv.y, acc4[h].y);
            acc4[h].z = fmaf(pw, vv.z, acc4[h].z);
            acc4[h].w = fmaf(pw, vv.w, acc4[h].w);
        }
    }

    // combine halves via smem (reuse qs: 128 t x 8 h x float4 = 16 KB)
    __syncthreads();
    float4* cb = reinterpret_cast<float4*>(qs);
    if (half == 1) {
        #pragma unroll
        for (int h = 0; h < NUM_HEADS; h++) cb[h * 128 + t] = acc4[h];
    }
    __syncthreads();
    if (half == 0) {
        float* o = g_pacc + (size_t)blockIdx.x * QROWS;
        #pragma unroll
        for (int h = 0; h < NUM_HEADS; h++) {
            float4 b = cb[h * 128 + t];
            float4 r = acc4[h];
            r.x += b.x; r.y += b.y; r.z += b.z; r.w += b.w;
            *reinterpret_cast<float4*>(o + h * HEAD_DIM + d) = r;
        }
    }
}

// ------------------------- kernel 3: single-pass weighted reduce -------------
// 128 blocks x 256 thr. Block b: head h=b/16, 8 float4 outputs (32 floats).
// Each thread: 16 independent LDG.128 over its 16 chunks; fixed-order tree.
__global__ void __launch_bounds__(256)
reduce_final() {
    const int b  = blockIdx.x;
    const int h  = b >> 4;
    const int f4base = b * 8;                  // float4 index into QROWS/4 = 1024

    __shared__ float red[8];
    __shared__ float sM, sL;
    __shared__ float w[NCHUNK];                // 2 KB
    __shared__ __align__(16) float4 part[32][8];
    const int lane = threadIdx.x & 31, warp = threadIdx.x >> 5;

    // global softmax stats for head h over 512 chunks (2 per thread)
    float m0 = g_pm[(threadIdx.x * 2) * NUM_HEADS + h];
    float m1 = g_pm[(threadIdx.x * 2 + 1) * NUM_HEADS + h];
    float m = warp_max(fmaxf(m0, m1));
    if (lane == 0) red[warp] = m;
    __syncthreads();
    if (threadIdx.x == 0) {
        float M = red[0];
        #pragma unroll
        for (int i = 1; i < 8; i++) M = fmaxf(M, red[i]);
        sM = M;
    }
    __syncthreads();
    float e0 = __expf(m0 - sM);
    float e1 = __expf(m1 - sM);
    float l = g_pl[(threadIdx.x * 2) * NUM_HEADS + h] * e0
            + g_pl[(threadIdx.x * 2 + 1) * NUM_HEADS + h] * e1;
    l = warp_sum(l);
    __syncthreads();
    if (lane == 0) red[warp] = l;
    __syncthreads();
    if (threadIdx.x == 0) {
        float L = 0.f;
        #pragma unroll
        for (int i = 0; i < 8; i++) L += red[i];
        sL = L;
    }
    __syncthreads();
    w[threadIdx.x * 2]     = e0 / sL;
    w[threadIdx.x * 2 + 1] = e1 / sL;
    __syncthreads();

    // weighted accumulation: thread t -> output f4o, chunk group cg (16 chunks)
    const int f4o = threadIdx.x & 7;
    const int cg  = threadIdx.x >> 3;          // 0..31
    const float4* pacc4 = reinterpret_cast<const float4*>(g_pacc);

    float4 s = make_float4(0.f, 0.f, 0.f, 0.f);
    #pragma unroll
    for (int k = 0; k < 16; k++) {
        int c = cg * 16 + k;
        float4 v = pacc4[(size_t)c * (QROWS / 4) + f4base + f4o];
        float wt = w[c];
        s.x = fmaf(wt, v.x, s.x);
        s.y = fmaf(wt, v.y, s.y);
        s.z = fmaf(wt, v.z, s.z);
        s.w = fmaf(wt, v.w, s.w);
    }
    part[cg][f4o] = s;
    __syncthreads();
    if (threadIdx.x < 8) {
        float4 acc = part[0][threadIdx.x];
        #pragma unroll
        for (int g = 1; g < 32; g++) {
            float4 v = part[g][threadIdx.x];
            acc.x += v.x; acc.y += v.y; acc.z += v.z; acc.w += v.w;
        }
        reinterpret_cast<float4*>(g_attn)[f4base + threadIdx.x] = acc;
    }
}

// ------------------------- kernel 4: output GEMV (warp-per-row) --------------
// 160 blocks x 512 threads = 2560 warps; warp w handles row w.
__global__ void __launch_bounds__(512)
wo_gemv(const float* __restrict__ wo, float* __restrict__ out) {
    int r = blockIdx.x * 16 + (threadIdx.x >> 5);
    int lane = threadIdx.x & 31;
    const float4* w4 = reinterpret_cast<const float4*>(wo + (size_t)r * QROWS);
    const float4* a4 = reinterpret_cast<const float4*>(g_attn);
    float s = 0.f;
    #pragma unroll
    for (int i = 0; i < QROWS / 4 / 32; i++) {      // 32 iterations
        float4 a = __ldcs(w4 + i * 32 + lane);
        float4 b = a4[i * 32 + lane];
        s += a.x * b.x + a.y * b.y + a.z * b.z + a.w * b.w;
    }
    s = warp_sum(s);
    if (lane == 0) out[r] = s;
}

// ------------------------- launch -------------------------------------------
extern "C" void kernel_launch(void* const* d_in, const int* in_sizes, int n_in,
                              void* d_out, int out_size) {
    const float* x       = (const float*)d_in[0];
    // d_in[1] = kv_sliding (unused by reference math)
    const float* kv_full = (const float*)d_in[2];
    const float* wq      = (const float*)d_in[3];
    const float* wk      = (const float*)d_in[4];
    const float* wv      = (const float*)d_in[5];
    const float* wo      = (const float*)d_in[6];
    const int*   curpos  = (const int*)d_in[7];
    // d_in[8] = ring_pos (unused)
    float* out = (float*)d_out;

    qkv_gemv<<<160, 1024>>>(x, wq, wk, wv);
    attn_chunk<<<NCHUNK, 256>>>(kv_full, curpos);
    reduce_final<<<128, 256>>>();
    wo_gemv<<<160, 512>>>(wo, out);
}

// round 8
// speedup vs baseline: 1.9227x; 1.0092x over previous
#include <cuda_runtime.h>
#include <cuda_bf16.h>
#include <math.h>

// Problem constants
#define HIDDEN    2560
#define NUM_HEADS 8
#define HEAD_DIM  512
#define SEQ       32768
#define QROWS     (NUM_HEADS * HEAD_DIM)   // 4096
#define SCALE     0.04419417382415922f     // 1/sqrt(512)

#define CHUNK     64                       // keys per attention block
#define NCHUNK    (SEQ / CHUNK)            // 512 blocks

// ------------------------- device scratch (no allocs allowed) ---------------
__device__ __align__(16) float g_q[QROWS];
__device__ __align__(16) float g_k[HEAD_DIM];
__device__ __align__(16) float g_v[HEAD_DIM];
__device__ float g_pm[NCHUNK * NUM_HEADS];          // per-chunk max
__device__ float g_pl[NCHUNK * NUM_HEADS];          // per-chunk expsum
__device__ __align__(16) float g_pacc[(size_t)NCHUNK * QROWS];    // 8 MB
__device__ __align__(16) float g_attn[QROWS];

// ------------------------- helpers ------------------------------------------
__device__ __forceinline__ float warp_sum(float v) {
    #pragma unroll
    for (int o = 16; o; o >>= 1) v += __shfl_xor_sync(0xffffffffu, v, o);
    return v;
}
__device__ __forceinline__ float warp_max(float v) {
    #pragma unroll
    for (int o = 16; o; o >>= 1) v = fmaxf(v, __shfl_xor_sync(0xffffffffu, v, o));
    return v;
}
__device__ __forceinline__ float4 ldcs4(const float* p) {
    return __ldcs(reinterpret_cast<const float4*>(p));
}

// ------------------------- kernel 1: fused QKV GEMV (2 warps per row) --------
// 640 blocks x 512 threads = 10240 warps; row r = gw/2, half = gw&1.
// Each warp: 10 independent float4 loads (160B in flight per lane).
__global__ void __launch_bounds__(512)
qkv_gemv(const float* __restrict__ x,
         const float* __restrict__ wq,
         const float* __restrict__ wk,
         const float* __restrict__ wv) {
    const int warp = threadIdx.x >> 5, lane = threadIdx.x & 31;
    const int gw = blockIdx.x * 16 + warp;
    const int r = gw >> 1, half = gw & 1;

    const float* w;
    float* outp;
    if (r < QROWS)            { w = wq + (size_t)r * HIDDEN;                 outp = g_q + r; }
    else if (r < QROWS + 512) { w = wk + (size_t)(r - QROWS) * HIDDEN;       outp = g_k + (r - QROWS); }
    else                      { w = wv + (size_t)(r - QROWS - 512) * HIDDEN; outp = g_v + (r - QROWS - 512); }

    const float4* w4 = reinterpret_cast<const float4*>(w);
    const float4* x4 = reinterpret_cast<const float4*>(x);
    const int base = half * (HIDDEN / 8);      // 320 float4 per half
    float s = 0.f;
    #pragma unroll
    for (int i = 0; i < HIDDEN / 8 / 32; i++) {    // 10 iterations
        float4 a = __ldcs(w4 + base + i * 32 + lane);
        float4 b = x4[base + i * 32 + lane];
        s += a.x * b.x + a.y * b.y + a.z * b.z + a.w * b.w;
    }
    s = warp_sum(s);

    __shared__ float part[16];
    if (lane == 0) part[warp] = s;
    __syncthreads();
    if (lane == 0 && half == 0)
        *outp = part[warp] + part[warp + 1];
}

// ------------------------- kernel 2: fused flash-decode chunk ----------------
// 512 blocks x 256 threads. Each block: 64 keys. (unchanged, known good)
__global__ void __launch_bounds__(256)
attn_chunk(const float* __restrict__ kv_full, const int* __restrict__ cur_pos) {
    __shared__ __align__(16) float qs[QROWS];          // 16 KB (reused as combine buf)
    __shared__ float p[NUM_HEADS][CHUNK];              // scores -> probs, 2 KB

    for (int i = threadIdx.x; i < QROWS; i += 256) qs[i] = g_q[i];
    __syncthreads();

    const int warp = threadIdx.x >> 5, lane = threadIdx.x & 31;
    const int cp = cur_pos[0];
    const int j0 = blockIdx.x * CHUNK;

    // ---- Phase A: scores (8 warps x 8 keys; 4 keys concurrently per warp) ----
    #pragma unroll
    for (int g = 0; g < 2; g++) {
        const int jj = warp * 8 + g * 4;
        const float* kr[4];
        #pragma unroll
        for (int t = 0; t < 4; t++) {
            int j = j0 + jj + t;
            kr[t] = (j == cp) ? g_k : (kv_full + (size_t)j * HEAD_DIM);
        }
        float acc[NUM_HEADS][4];
        #pragma unroll
        for (int h = 0; h < NUM_HEADS; h++)
            #pragma unroll
            for (int t = 0; t < 4; t++) acc[h][t] = 0.f;

        #pragma unroll
        for (int i = 0; i < 4; i++) {
            int d = i * 128 + lane * 4;
            float4 kv0 = ldcs4(kr[0] + d);
            float4 kv1 = ldcs4(kr[1] + d);
            float4 kv2 = ldcs4(kr[2] + d);
            float4 kv3 = ldcs4(kr[3] + d);
            #pragma unroll
            for (int h = 0; h < NUM_HEADS; h++) {
                float4 qv = *reinterpret_cast<const float4*>(qs + h * HEAD_DIM + d);
                acc[h][0] += qv.x * kv0.x + qv.y * kv0.y + qv.z * kv0.z + qv.w * kv0.w;
                acc[h][1] += qv.x * kv1.x + qv.y * kv1.y + qv.z * kv1.z + qv.w * kv1.w;
                acc[h][2] += qv.x * kv2.x + qv.y * kv2.y + qv.z * kv2.z + qv.w * kv2.w;
                acc[h][3] += qv.x * kv3.x + qv.y * kv3.y + qv.z * kv3.z + qv.w * kv3.w;
            }
        }
        #pragma unroll
        for (int h = 0; h < NUM_HEADS; h++) {
            #pragma unroll
            for (int t = 0; t < 4; t++) {
                float s = warp_sum(acc[h][t]);
                if (lane == 0) p[h][jj + t] = s * SCALE;
            }
        }
    }
    __syncthreads();

    // ---- Phase B: local softmax stats (warp h handles head h) ----
    {
        const int h = warp;
        float a = p[h][lane];
        float b = p[h][lane + 32];
        float m = warp_max(fmaxf(a, b));
        float ea = __expf(a - m);
        float eb = __expf(b - m);
        float l = warp_sum(ea + eb);
        p[h][lane]      = ea;
        p[h][lane + 32] = eb;
        if (lane == 0) {
            g_pm[blockIdx.x * NUM_HEADS + h] = m;
            g_pl[blockIdx.x * NUM_HEADS + h] = l;
        }
    }
    __syncthreads();

    // ---- Phase C: P @ V partial (float4, jj split across thread halves) ----
    const int half = threadIdx.x >> 7;          // 0 or 1
    const int t    = threadIdx.x & 127;
    const int d    = t * 4;
    const int jbase = half * 32;
    const float* vcache = kv_full + (size_t)SEQ * HEAD_DIM;

    float4 acc4[NUM_HEADS];
    #pragma unroll
    for (int h = 0; h < NUM_HEADS; h++) acc4[h] = make_float4(0.f, 0.f, 0.f, 0.f);

    #pragma unroll 8
    for (int jj = 0; jj < 32; jj++) {
        int j = j0 + jbase + jj;
        const float* vrow = (j == cp) ? g_v : (vcache + (size_t)j * HEAD_DIM);
        float4 vv = ldcs4(vrow + d);
        #pragma unroll
        for (int h = 0; h < NUM_HEADS; h++) {
            float pw = p[h][jbase + jj];
            acc4[h].x = fmaf(pw, vv.x, acc4[h].x);
            acc4[h].y = fmaf(pw, vv.y, acc4[h].y);
            acc4[h].z = fmaf(pw, vv.z, acc4[h].z);
            acc4[h].w = fmaf(pw, vv.w, acc4[h].w);
        }
    }

    // combine halves via smem (reuse qs: 128 t x 8 h x float4 = 16 KB)
    __syncthreads();
    float4* cb = reinterpret_cast<float4*>(qs);
    if (half == 1) {
        #pragma unroll
        for (int h = 0; h < NUM_HEADS; h++) cb[h * 128 + t] = acc4[h];
    }
    __syncthreads();
    if (half == 0) {
        float* o = g_pacc + (size_t)blockIdx.x * QROWS;
        #pragma unroll
        for (int h = 0; h < NUM_HEADS; h++) {
            float4 b = cb[h * 128 + t];
            float4 r = acc4[h];
            r.x += b.x; r.y += b.y; r.z += b.z; r.w += b.w;
            *reinterpret_cast<float4*>(o + h * HEAD_DIM + d) = r;
        }
    }
}

// ------------------------- kernel 3: single-pass weighted reduce -------------
// 128 blocks x 256 thr. Block b: head h=b/16, 8 float4 outputs (32 floats).
__global__ void __launch_bounds__(256)
reduce_final() {
    const int b  = blockIdx.x;
    const int h  = b >> 4;
    const int f4base = b * 8;                  // float4 index into QROWS/4 = 1024

    __shared__ float red[8];
    __shared__ float sM, sL;
    __shared__ float w[NCHUNK];                // 2 KB
    __shared__ __align__(16) float4 part[32][8];
    const int lane = threadIdx.x & 31, warp = threadIdx.x >> 5;

    // global softmax stats for head h over 512 chunks (2 per thread)
    float m0 = g_pm[(threadIdx.x * 2) * NUM_HEADS + h];
    float m1 = g_pm[(threadIdx.x * 2 + 1) * NUM_HEADS + h];
    float m = warp_max(fmaxf(m0, m1));
    if (lane == 0) red[warp] = m;
    __syncthreads();
    if (threadIdx.x == 0) {
        float M = red[0];
        #pragma unroll
        for (int i = 1; i < 8; i++) M = fmaxf(M, red[i]);
        sM = M;
    }
    __syncthreads();
    float e0 = __expf(m0 - sM);
    float e1 = __expf(m1 - sM);
    float l = g_pl[(threadIdx.x * 2) * NUM_HEADS + h] * e0
            + g_pl[(threadIdx.x * 2 + 1) * NUM_HEADS + h] * e1;
    l = warp_sum(l);
    __syncthreads();
    if (lane == 0) red[warp] = l;
    __syncthreads();
    if (threadIdx.x == 0) {
        float L = 0.f;
        #pragma unroll
        for (int i = 0; i < 8; i++) L += red[i];
        sL = L;
    }
    __syncthreads();
    w[threadIdx.x * 2]     = e0 / sL;
    w[threadIdx.x * 2 + 1] = e1 / sL;
    __syncthreads();

    const int f4o = threadIdx.x & 7;
    const int cg  = threadIdx.x >> 3;          // 0..31
    const float4* pacc4 = reinterpret_cast<const float4*>(g_pacc);

    float4 s = make_float4(0.f, 0.f, 0.f, 0.f);
    #pragma unroll
    for (int k = 0; k < 16; k++) {
        int c = cg * 16 + k;
        float4 v = pacc4[(size_t)c * (QROWS / 4) + f4base + f4o];
        float wt = w[c];
        s.x = fmaf(wt, v.x, s.x);
        s.y = fmaf(wt, v.y, s.y);
        s.z = fmaf(wt, v.z, s.z);
        s.w = fmaf(wt, v.w, s.w);
    }
    part[cg][f4o] = s;
    __syncthreads();
    if (threadIdx.x < 8) {
        float4 acc = part[0][threadIdx.x];
        #pragma unroll
        for (int g = 1; g < 32; g++) {
            float4 v = part[g][threadIdx.x];
            acc.x += v.x; acc.y += v.y; acc.z += v.z; acc.w += v.w;
        }
        reinterpret_cast<float4*>(g_attn)[f4base + threadIdx.x] = acc;
    }
}

// ------------------------- kernel 4: output GEMV (2 warps per row) -----------
// 320 blocks x 512 threads = 5120 warps; row r = gw/2, half = gw&1.
// Each warp: 16 independent float4 loads (256B in flight per lane).
__global__ void __launch_bounds__(512)
wo_gemv(const float* __restrict__ wo, float* __restrict__ out) {
    const int warp = threadIdx.x >> 5, lane = threadIdx.x & 31;
    const int gw = blockIdx.x * 16 + warp;
    const int r = gw >> 1, half = gw & 1;

    const float4* w4 = reinterpret_cast<const float4*>(wo + (size_t)r * QROWS);
    const float4* a4 = reinterpret_cast<const float4*>(g_attn);
    const int base = half * (QROWS / 8);       // 512 float4 per half
    float s = 0.f;
    #pragma unroll
    for (int i = 0; i < QROWS / 8 / 32; i++) {     // 16 iterations
        float4 a = __ldcs(w4 + base + i * 32 + lane);
        float4 b = a4[base + i * 32 + lane];
        s += a.x * b.x + a.y * b.y + a.z * b.z + a.w * b.w;
    }
    s = warp_sum(s);

    __shared__ float part[16];
    if (lane == 0) part[warp] = s;
    __syncthreads();
    if (lane == 0 && half == 0)
        out[r] = part[warp] + part[warp + 1];
}

// ------------------------- launch -------------------------------------------
extern "C" void kernel_launch(void* const* d_in, const int* in_sizes, int n_in,
                              void* d_out, int out_size) {
    const float* x       = (const float*)d_in[0];
    // d_in[1] = kv_sliding (unused by reference math)
    const float* kv_full = (const float*)d_in[2];
    const float* wq      = (const float*)d_in[3];
    const float* wk      = (const float*)d_in[4];
    const float* wv      = (const float*)d_in[5];
    const float* wo      = (const float*)d_in[6];
    const int*   curpos  = (const int*)d_in[7];
    // d_in[8] = ring_pos (unused)
    float* out = (float*)d_out;

    qkv_gemv<<<640, 512>>>(x, wq, wk, wv);
    attn_chunk<<<NCHUNK, 256>>>(kv_full, curpos);
    reduce_final<<<128, 256>>>();
    wo_gemv<<<320, 512>>>(wo, out);
}